// round 2
// baseline (speedup 1.0000x reference)
#include <cuda_runtime.h>
#include <stdint.h>

#define BSZ  16384
#define KC   8192
#define MAXC 100
#define MINC 20
#define NT   256
#define PER  (KC / NT)   // 32 elements per thread

__global__ __launch_bounds__(NT) void retention_kernel(
    const float* __restrict__ logits, float* __restrict__ out)
{
    __shared__ uint32_t skeys[KC];     // 32 KB row cache (sortable keys)
    __shared__ int      sbins[256];
    __shared__ int      sgt[NT], seq[NT];
    __shared__ int      s_above;
    __shared__ uint32_t s_prefix;
    __shared__ int      s_r;

    const int row  = blockIdx.x;
    const int tid  = threadIdx.x;
    const int lane = tid & 31;

    if (tid == 0) s_above = 0;
    __syncthreads();

    // ---- Phase 0: load row, make order-preserving keys, count logits >= 0 ----
    const float4* in4 = (const float4*)(logits + (size_t)row * KC);
    uint4* sk4 = (uint4*)skeys;
    int cnt = 0;
    #pragma unroll
    for (int i = 0; i < PER / 4; i++) {
        int v = tid + i * NT;
        float4 f = in4[v];
        uint4 kk; uint32_t u;
        u = __float_as_uint(f.x); kk.x = ((int)u < 0) ? ~u : (u | 0x80000000u); cnt += (f.x >= 0.f);
        u = __float_as_uint(f.y); kk.y = ((int)u < 0) ? ~u : (u | 0x80000000u); cnt += (f.y >= 0.f);
        u = __float_as_uint(f.z); kk.z = ((int)u < 0) ? ~u : (u | 0x80000000u); cnt += (f.z >= 0.f);
        u = __float_as_uint(f.w); kk.w = ((int)u < 0) ? ~u : (u | 0x80000000u); cnt += (f.w >= 0.f);
        sk4[v] = kk;
    }
    cnt = __reduce_add_sync(0xFFFFFFFFu, cnt);
    if (lane == 0) atomicAdd(&s_above, cnt);
    __syncthreads();

    const int ktrain = min(max(s_above, MINC), MAXC);

    // ---- Phases 1-4: radix-select the ktrain-th largest 32-bit key ----
    uint32_t prefix = 0;
    int r = ktrain;
    for (int pass = 0; pass < 4; pass++) {
        const int shift = 24 - pass * 8;
        sbins[tid] = 0;
        __syncthreads();

        for (int i = tid; i < KC; i += NT) {
            uint32_t key = skeys[i];
            // ((key>>shift)>>8) avoids shift-by-32 UB at pass 0
            bool m = (((key >> shift) >> 8) == prefix);
            uint32_t bin = m ? ((key >> shift) & 0xFFu) : 0xFFFFFFFFu;
            // warp-aggregate same-bin lanes: concentrated exponent bytes would
            // otherwise serialize the smem atomic unit
            unsigned grp = __match_any_sync(0xFFFFFFFFu, bin);
            if (m && lane == (__ffs(grp) - 1))
                atomicAdd(&sbins[bin], __popc(grp));
        }
        __syncthreads();

        // parallel suffix scan over the 256 bins (descending cumulative)
        int own = sbins[tid];
        __syncthreads();
        for (int off = 1; off < 256; off <<= 1) {
            int v = (tid + off < 256) ? sbins[tid + off] : 0;
            __syncthreads();
            sbins[tid] += v;
            __syncthreads();
        }
        int incl  = sbins[tid];      // keys in bins >= tid (under prefix)
        int above = incl - own;      // keys in bins >  tid
        if (incl >= r && above < r) {   // unique owning bin
            s_prefix = (prefix << 8) | (uint32_t)tid;
            s_r = r - above;
        }
        __syncthreads();
        prefix = s_prefix;
        r = s_r;
        __syncthreads();
    }

    const uint32_t T = prefix;   // exact key of the ktrain-th largest element
    const int need_eq = r;       // how many key==T (lowest indices) to include

    // ---- Phase 5: per-chunk (32 contiguous indices) counts + block scans ----
    const int base = tid * PER;
    int gt = 0, eq = 0;
    #pragma unroll
    for (int j = 0; j < PER; j++) {
        uint32_t key = skeys[base + ((j + tid) & (PER - 1))];  // conflict-free swizzle
        gt += (key > T);
        eq += (key == T);
    }
    sgt[tid] = gt; seq[tid] = eq;
    __syncthreads();
    for (int off = 1; off < NT; off <<= 1) {
        int g = (tid >= off) ? sgt[tid - off] : 0;
        int e = (tid >= off) ? seq[tid - off] : 0;
        __syncthreads();
        sgt[tid] += g; seq[tid] += e;
        __syncthreads();
    }
    const int gt_excl = sgt[tid] - gt;
    const int eq_excl = seq[tid] - eq;

    // Output: three float32 sections, each [BSZ, MAXC]: bs_idx | cls_idx | mask
    float* __restrict__ bs_out  = out;
    float* __restrict__ cls_out = out + (size_t)BSZ * MAXC;
    float* __restrict__ msk_out = out + (size_t)2 * BSZ * MAXC;
    const size_t rbase = (size_t)row * MAXC;

    // ---- Emission: ascending class-index order == reference's sorted output ----
    #pragma unroll
    for (int j = 0; j < PER; j++) {
        const int lj = (j + tid) & (PER - 1);
        uint32_t key = skeys[base + lj];
        if (key >= T) {
            // rare path (~100 elems/row): recount local in-chunk prefix
            int lgt = 0, leq = 0;
            for (int m = 0; m < lj; m++) {
                uint32_t k2 = skeys[base + m];
                lgt += (k2 > T);
                leq += (k2 == T);
            }
            int gtb = gt_excl + lgt;         // # key>T at smaller index
            int eqb = eq_excl + leq;         // # key==T at smaller index
            if (key > T) {
                int pos = gtb + min(eqb, need_eq);
                cls_out[rbase + pos] = (float)(base + lj);
            } else if (eqb < need_eq) {      // tie-break: lowest indices win
                cls_out[rbase + (gtb + eqb)] = (float)(base + lj);
            }
        }
    }

    // ---- Padding / bs_idx / mask (disjoint positions, no ordering hazard) ----
    if (tid < MAXC) {
        bs_out[rbase + tid]  = (tid < ktrain) ? (float)row : -1.0f;
        if (tid >= ktrain) cls_out[rbase + tid] = -1.0f;
        msk_out[rbase + tid] = (tid < ktrain) ? 1.0f : 0.0f;
    }
}

extern "C" void kernel_launch(void* const* d_in, const int* in_sizes, int n_in,
                              void* d_out, int out_size)
{
    const float* logits = (const float*)d_in[0];
    float* out = (float*)d_out;
    retention_kernel<<<BSZ, NT>>>(logits, out);
}

// round 3
// speedup vs baseline: 2.5079x; 2.5079x over previous
#include <cuda_runtime.h>
#include <stdint.h>

#define BSZ  16384
#define KC   8192
#define MAXC 100
#define MINC 20
#define NT   256
#define PER  32
#define CAP  512          // candidate buffer capacity

// sum over threads with tid' > tid (block-wide exclusive suffix). 2 barriers.
__device__ __forceinline__ int block_suffix_excl(int v, int tid, volatile int* wtmp) {
    int lane = tid & 31, w = tid >> 5;
    int x = v;
    #pragma unroll
    for (int off = 1; off < 32; off <<= 1) {
        int t = __shfl_down_sync(0xFFFFFFFFu, x, off);
        if (lane + off < 32) x += t;
    }
    if (lane == 0) wtmp[w] = x;          // lane0 inclusive-suffix == warp total
    __syncthreads();
    int above = 0;
    #pragma unroll
    for (int j = 0; j < 8; j++) above += (j > w) ? wtmp[j] : 0;
    __syncthreads();
    return above + (x - v);
}

// sum over threads with tid' < tid (block-wide exclusive prefix). 2 barriers.
__device__ __forceinline__ int block_prefix_excl(int v, int tid, volatile int* wtmp) {
    int lane = tid & 31, w = tid >> 5;
    int x = v;
    #pragma unroll
    for (int off = 1; off < 32; off <<= 1) {
        int t = __shfl_up_sync(0xFFFFFFFFu, x, off);
        if (lane >= off) x += t;
    }
    if (lane == 31) wtmp[w] = x;
    __syncthreads();
    int below = 0;
    #pragma unroll
    for (int j = 0; j < 8; j++) below += (j < w) ? wtmp[j] : 0;
    __syncthreads();
    return below + (x - v);
}

__global__ __launch_bounds__(NT, 4) void retention_kernel(
    const float* __restrict__ logits, float* __restrict__ out)
{
    __shared__ uint32_t skeys[KC];      // 32 KB row cache (sortable keys)
    __shared__ int      hist[2048];     // 8 KB: 11-bit hist, then sub-pass hists
    __shared__ uint32_t cand[CAP];      // 2 KB boundary-bin candidates
    __shared__ int      wtmp[8];
    __shared__ int      s_above, sW;
    __shared__ int      s_b, s_need, s_d1, s_need2, s_d0, s_neq;

    const int row  = blockIdx.x;
    const int tid  = threadIdx.x;
    const int lane = tid & 31;
    const int4 z4  = make_int4(0, 0, 0, 0);

    ((int4*)hist)[tid]       = z4;      // zero 2048 bins
    ((int4*)hist)[tid + 256] = z4;
    if (tid == 0) { s_above = 0; sW = 0; }
    __syncthreads();

    // ---- Phase 0 (fused): load row, make keys, count >=0, 11-bit histogram ----
    const float4* in4 = (const float4*)(logits + (size_t)row * KC);
    uint4* sk4 = (uint4*)skeys;
    int cnt = 0;
    #pragma unroll
    for (int i = 0; i < PER / 4; i++) {
        int v = tid + i * NT;
        float4 f = in4[v];
        uint4 kk; uint32_t u;
        u = __float_as_uint(f.x); kk.x = ((int)u < 0) ? ~u : (u | 0x80000000u); cnt += (f.x >= 0.f);
        u = __float_as_uint(f.y); kk.y = ((int)u < 0) ? ~u : (u | 0x80000000u); cnt += (f.y >= 0.f);
        u = __float_as_uint(f.z); kk.z = ((int)u < 0) ? ~u : (u | 0x80000000u); cnt += (f.z >= 0.f);
        u = __float_as_uint(f.w); kk.w = ((int)u < 0) ? ~u : (u | 0x80000000u); cnt += (f.w >= 0.f);
        sk4[v] = kk;
        #pragma unroll
        for (int c = 0; c < 4; c++) {
            uint32_t key = (c == 0) ? kk.x : (c == 1) ? kk.y : (c == 2) ? kk.z : kk.w;
            uint32_t bin = key >> 21;
            unsigned grp = __match_any_sync(0xFFFFFFFFu, bin);   // warp-aggregate
            if (lane == (__ffs(grp) - 1)) atomicAdd(&hist[bin], __popc(grp));
        }
    }
    cnt = __reduce_add_sync(0xFFFFFFFFu, cnt);
    if (lane == 0) atomicAdd(&s_above, cnt);
    __syncthreads();

    const int ktrain = min(max(s_above, MINC), MAXC);

    // ---- Find boundary bin b: largest b with count(bin>=b) >= k ----
    const int base8 = tid * 8;
    {
        int local = 0;
        #pragma unroll
        for (int j = 0; j < 8; j++) local += hist[base8 + j];
        int above = block_suffix_excl(local, tid, wtmp);
        if (above < ktrain && above + local >= ktrain) {
            int run = above;
            for (int j = 7; j >= 0; j--) {
                int c = hist[base8 + j];
                if (run < ktrain && run + c >= ktrain) { s_b = base8 + j; s_need = ktrain - run; }
                run += c;
            }
        }
    }
    __syncthreads();
    const int b = s_b, need = s_need;

    // ---- Compact boundary-bin candidates (ballot-aggregated) ----
    const int base = tid * PER;
    #pragma unroll 1
    for (int j = 0; j < PER; j++) {
        int lj = (j + tid) & (PER - 1);                  // conflict-free swizzle
        uint32_t key = skeys[base + lj];
        bool p = ((int)(key >> 21) == b);
        unsigned m = __ballot_sync(0xFFFFFFFFu, p);
        if (p) {
            int leader = __ffs(m) - 1;
            int prev   = __popc(m & ((1u << lane) - 1));
            int pos;
            if (lane == leader) pos = atomicAdd(&sW, __popc(m));
            pos = __shfl_sync(m, pos, leader);
            int my = pos + prev;
            if (my < CAP) cand[my] = key;
        }
    }
    __syncthreads();
    const int W = sW;
    const bool fits = (W <= CAP);

    // ---- Sub-pass 1: bits [20:10] (2048 bins) over candidates only ----
    ((int4*)hist)[tid] = z4; ((int4*)hist)[tid + 256] = z4;
    __syncthreads();
    if (fits) {
        for (int i = tid; i < W; i += NT)
            atomicAdd(&hist[(cand[i] >> 10) & 0x7FF], 1);
    } else {                                            // overflow fallback: full scan
        for (int i = tid; i < KC; i += NT) {
            uint32_t key = skeys[i];
            if ((int)(key >> 21) == b) atomicAdd(&hist[(key >> 10) & 0x7FF], 1);
        }
    }
    __syncthreads();
    {
        int local = 0;
        #pragma unroll
        for (int j = 0; j < 8; j++) local += hist[base8 + j];
        int above = block_suffix_excl(local, tid, wtmp);
        if (above < need && above + local >= need) {
            int run = above;
            for (int j = 7; j >= 0; j--) {
                int c = hist[base8 + j];
                if (run < need && run + c >= need) { s_d1 = base8 + j; s_need2 = need - run; }
                run += c;
            }
        }
    }
    __syncthreads();
    const int need2 = s_need2;
    const uint32_t pref22 = ((uint32_t)b << 11) | (uint32_t)s_d1;

    // ---- Sub-pass 2: bits [9:0] (1024 bins) ----
    ((int4*)hist)[tid] = z4;
    __syncthreads();
    if (fits) {
        for (int i = tid; i < W; i += NT) {
            uint32_t c = cand[i];
            if ((c >> 10) == pref22) atomicAdd(&hist[c & 0x3FF], 1);
        }
    } else {
        for (int i = tid; i < KC; i += NT) {
            uint32_t key = skeys[i];
            if ((key >> 10) == pref22) atomicAdd(&hist[key & 0x3FF], 1);
        }
    }
    __syncthreads();
    {
        const int base4 = tid * 4;
        int local = 0;
        #pragma unroll
        for (int j = 0; j < 4; j++) local += hist[base4 + j];
        int above = block_suffix_excl(local, tid, wtmp);
        if (above < need2 && above + local >= need2) {
            int run = above;
            for (int j = 3; j >= 0; j--) {
                int c = hist[base4 + j];
                if (run < need2 && run + c >= need2) { s_d0 = base4 + j; s_neq = need2 - run; }
                run += c;
            }
        }
    }
    __syncthreads();
    const uint32_t T = (pref22 << 10) | (uint32_t)s_d0;  // exact k-th largest key
    const int need_eq = s_neq;                           // # of ==T (lowest idx) kept

    // ---- Per-chunk gt/eq counts + packed block prefix scan ----
    int gt = 0, eq = 0;
    #pragma unroll 8
    for (int j = 0; j < PER; j++) {
        uint32_t key = skeys[base + ((j + tid) & (PER - 1))];
        gt += (key > T);
        eq += (key == T);
    }
    int excl = block_prefix_excl((gt << 16) | eq, tid, wtmp);
    const int gt_excl = excl >> 16;
    const int eq_excl = excl & 0xFFFF;

    // Output: three float32 sections, each [BSZ, MAXC]: bs_idx | cls_idx | mask
    float* __restrict__ bs_out  = out;
    float* __restrict__ cls_out = out + (size_t)BSZ * MAXC;
    float* __restrict__ msk_out = out + (size_t)2 * BSZ * MAXC;
    const size_t rbase = (size_t)row * MAXC;

    // ---- Emission: ascending class-index order == reference's sorted output ----
    #pragma unroll 1
    for (int j = 0; j < PER; j++) {
        const int lj = (j + tid) & (PER - 1);
        uint32_t key = skeys[base + lj];
        if (key >= T) {
            int lgt = 0, leq = 0;                        // rare (~100/row)
            for (int m2 = 0; m2 < lj; m2++) {
                uint32_t k2 = skeys[base + m2];
                lgt += (k2 > T);
                leq += (k2 == T);
            }
            int gtb = gt_excl + lgt;
            int eqb = eq_excl + leq;
            if (key > T) {
                cls_out[rbase + gtb + min(eqb, need_eq)] = (float)(base + lj);
            } else if (eqb < need_eq) {
                cls_out[rbase + gtb + eqb] = (float)(base + lj);
            }
        }
    }

    // ---- Padding / bs_idx / mask ----
    if (tid < MAXC) {
        bs_out[rbase + tid] = (tid < ktrain) ? (float)row : -1.0f;
        if (tid >= ktrain) cls_out[rbase + tid] = -1.0f;
        msk_out[rbase + tid] = (tid < ktrain) ? 1.0f : 0.0f;
    }
}

extern "C" void kernel_launch(void* const* d_in, const int* in_sizes, int n_in,
                              void* d_out, int out_size)
{
    const float* logits = (const float*)d_in[0];
    float* out = (float*)d_out;
    retention_kernel<<<BSZ, NT>>>(logits, out);
}